// round 6
// baseline (speedup 1.0000x reference)
#include <cuda_runtime.h>
#include <cstdint>

// out = x + exp(0.5*(relu(x@W1+b1)@W2 + b2)) * eps
// x,eps,out [B,256] f32; W1 [256,64]; b1[64]; W2 [64,256]; b2[256]
// Persistent warp-specialized mma.sync tf32 kernel:
//   warps 0-7  (producer): X cp.async ring + GEMM1 + relu -> H (2 buffers)
//   warps 8-15 (consumer): GEMM2 + fused epilogue
#define SDIM 256
#define HDIM 64
#define TMR  128
#define NTHREADS 512

// smem float-index offsets
#define W1F 0          // W1 tf32 [k=256][64] XOR-swizzled   (64 KB)
#define W2F 16384      // W2 tf32 [k=64][256] XOR-swizzled   (64 KB)
#define XS0 32768      // X chunk slot0: 128 rows x 32 k     (16 KB)
#define XS1 36864      // slot1                              (16 KB)
#define H0F 40960      // H buffer 0: 128 x 64 tf32          (32 KB)
#define H1F 49152      // H buffer 1                         (32 KB)
#define B1S 57344      // 64 f32
#define B2S 57408      // 256 f32
#define MBF 57664      // 4 mbarriers (8B each) = 8 floats
#define SMEM_FLOATS 57672
#define SMEM_BYTES  (SMEM_FLOATS * 4)   // 230688 <= 232448 cap

__device__ __forceinline__ uint32_t to_tf32(float f) {
    uint32_t r; asm("cvt.rna.tf32.f32 %0, %1;" : "=r"(r) : "f"(f)); return r;
}
__device__ __forceinline__ float ex2f(float f) {
    float r; asm("ex2.approx.f32 %0, %1;" : "=f"(r) : "f"(f)); return r;
}
__device__ __forceinline__ void mma8(float* c,
    uint32_t a0, uint32_t a1, uint32_t a2, uint32_t a3, uint32_t b0, uint32_t b1) {
    asm volatile(
        "mma.sync.aligned.m16n8k8.row.col.f32.tf32.tf32.f32 "
        "{%0,%1,%2,%3},{%4,%5,%6,%7},{%8,%9},{%0,%1,%2,%3};"
        : "+f"(c[0]), "+f"(c[1]), "+f"(c[2]), "+f"(c[3])
        : "r"(a0), "r"(a1), "r"(a2), "r"(a3), "r"(b0), "r"(b1));
}
static __device__ __forceinline__ uint32_t smem_u32(const void* p) {
    uint32_t a;
    asm("{ .reg .u64 t; cvta.to.shared.u64 t, %1; cvt.u32.u64 %0, t; }" : "=r"(a) : "l"(p));
    return a;
}
#define CPA16(s, g)  asm volatile("cp.async.cg.shared.global [%0], [%1], 16;" :: "r"(s), "l"(g))
#define CPCOMMIT()   asm volatile("cp.async.commit_group;" ::: "memory")
#define CPWAIT1()    asm volatile("cp.async.wait_group 1;" ::: "memory")
#define BARP()       asm volatile("bar.sync 1, 256;" ::: "memory")   // producer group only

#define MBAR_INIT(a, c) \
    asm volatile("mbarrier.init.shared.b64 [%0], %1;" :: "r"(a), "r"((uint32_t)(c)) : "memory")
#define MBAR_ARRIVE(a) \
    asm volatile("mbarrier.arrive.shared.b64 _, [%0];" :: "r"(a) : "memory")
#define MBAR_WAIT(a, ph) do { \
    uint32_t _m = (a); uint32_t _p = (uint32_t)(ph); uint32_t _d; \
    asm volatile("{\n\t.reg .pred p;\n\t" \
        "mbarrier.try_wait.parity.acquire.cta.shared::cta.b64 p, [%1], %2;\n\t" \
        "selp.b32 %0, 1, 0, p;\n\t}" : "=r"(_d) : "r"(_m), "r"(_p) : "memory"); \
    if (!_d) { \
        asm volatile("{\n\t.reg .pred P1;\n\t" \
            "WL_%=:\n\t" \
            "mbarrier.try_wait.parity.acquire.cta.shared::cta.b64 P1, [%0], %1, 0x989680;\n\t" \
            "@P1 bra.uni WD_%=;\n\t" \
            "bra.uni WL_%=;\n\t" \
            "WD_%=:\n\t}" :: "r"(_m), "r"(_p) : "memory"); \
    } \
} while (0)

// load one X chunk (128 rows x 32 floats) into a swizzled 16KB slot (producer: 256 thr)
static __device__ __forceinline__ void load_chunk32(
    const float* __restrict__ xT, int ck, float* slot, int ptid) {
    const float* gsrc = xT + ck * 32;
    #pragma unroll
    for (int j = 0; j < 4; j++) {
        int f = ptid + 256 * j;          // float4 index, 1024 total
        int m = f >> 3, c4 = f & 7;
        uint32_t dst = smem_u32(slot + m * 32 + 4 * (c4 ^ (m & 7)));
        CPA16(dst, gsrc + m * SDIM + 4 * c4);
    }
}

__global__ void __launch_bounds__(NTHREADS, 1) mvn_ws_kernel(
    const float* __restrict__ x, const float* __restrict__ eps,
    const float* __restrict__ W1, const float* __restrict__ b1,
    const float* __restrict__ W2, const float* __restrict__ b2,
    float* __restrict__ out, int numTiles)
{
    extern __shared__ float sm[];
    uint32_t* smu = reinterpret_cast<uint32_t*>(sm);

    const int tid  = threadIdx.x;
    const int wh   = (tid >> 5) & 7;   // row-group within its warp group
    const int lane = tid & 31;
    const int g    = lane >> 2;
    const int t4   = lane & 3;
    const bool isProd = (tid < 256);
    const int ptid = tid & 255;

    const uint32_t mb_full0  = smem_u32(sm + MBF) + 0;
    const uint32_t mb_full1  = smem_u32(sm + MBF) + 8;
    const uint32_t mb_empty0 = smem_u32(sm + MBF) + 16;
    const uint32_t mb_empty1 = smem_u32(sm + MBF) + 24;

    // ---- stage weights (tf32, XOR-swizzled) + biases ----
    #pragma unroll 4
    for (int j = 0; j < 32; j++) {
        int idx = tid + NTHREADS * j;
        int kk = idx >> 6, n = idx & 63;
        smu[W1F + kk * 64 + (n ^ (8 * (kk & 3)))] = to_tf32(W1[idx]);
    }
    #pragma unroll 4
    for (int j = 0; j < 32; j++) {
        int idx = tid + NTHREADS * j;
        int kk = idx >> 8, n = idx & 255;
        smu[W2F + kk * 256 + (n ^ (8 * (kk & 3)))] = to_tf32(W2[idx]);
    }
    if (tid < 64) sm[B1S + tid] = b1[tid];
    if (tid >= 64 && tid < 320) sm[B2S + tid - 64] = b2[tid - 64];
    if (tid == 0) {
        MBAR_INIT(mb_full0, 256);  MBAR_INIT(mb_full1, 256);   // producers arrive
        MBAR_INIT(mb_empty0, 256); MBAR_INIT(mb_empty1, 256);  // consumers arrive
    }
    __syncthreads();   // last block-wide barrier

    const int G = gridDim.x;
    const long long TS = (long long)TMR * SDIM;

    if (isProd) {
        // ================= PRODUCER =================
        const int arow32 = (16 * wh + g) * 32 + t4;
        int t = blockIdx.x;
        load_chunk32(x + t * TS, 0, sm + XS0, ptid); CPCOMMIT();
        load_chunk32(x + t * TS, 1, sm + XS1, ptid); CPCOMMIT();
        int buf = 0;
        int pe0 = 1, pe1 = 1;

        for (; t < numTiles; t += G) {
            const float* xT = x + t * TS;
            float acc1[8][4];
            #pragma unroll
            for (int nt = 0; nt < 8; nt++)
                acc1[nt][0] = acc1[nt][1] = acc1[nt][2] = acc1[nt][3] = 0.0f;

            #pragma unroll
            for (int c = 0; c < 8; c++) {
                CPWAIT1();
                BARP();                       // chunk c visible to all producers
                const float* xs = sm + ((c & 1) ? XS1 : XS0);
                #pragma unroll
                for (int ks = 0; ks < 4; ks++) {
                    int a0i = arow32 + 4 * ((2 * ks) ^ g);
                    uint32_t A0 = to_tf32(xs[a0i]);
                    uint32_t A1 = to_tf32(xs[a0i + 256]);
                    uint32_t A2 = to_tf32(xs[a0i ^ 4]);
                    uint32_t A3 = to_tf32(xs[(a0i ^ 4) + 256]);
                    const uint32_t* bp = smu + W1F + (32 * c + 8 * ks + t4) * 64 + g;
                    #pragma unroll
                    for (int nt = 0; nt < 8; nt++) {
                        int o = 8 * (nt ^ t4);
                        mma8(acc1[nt], A0, A1, A2, A3, bp[o], bp[o + 256]);
                    }
                }
                BARP();                       // all producers done with slot
                int nc = c + 2;
                float* slot = sm + ((c & 1) ? XS1 : XS0);
                if (nc < 8) {
                    load_chunk32(xT, nc, slot, ptid);
                } else {
                    int tn = t + G;
                    if (tn < numTiles) load_chunk32(x + tn * TS, nc - 8, slot, ptid);
                }
                CPCOMMIT();                   // uniform group count
            }

            // acquire H buffer, store relu(acc + b1) as tf32
            if (buf == 0) { MBAR_WAIT(mb_empty0, pe0); pe0 ^= 1; }
            else          { MBAR_WAIT(mb_empty1, pe1); pe1 ^= 1; }
            uint32_t* Hb = smu + (buf ? H1F : H0F);
            const int m0 = (16 * wh + g) * 64;
            #pragma unroll
            for (int nt = 0; nt < 8; nt++) {
                int col = 8 * nt + 2 * t4;
                float2 bb = *reinterpret_cast<const float2*>(&sm[B1S + col]);
                uint2 p0, p1;
                p0.x = to_tf32(fmaxf(acc1[nt][0] + bb.x, 0.0f));
                p0.y = to_tf32(fmaxf(acc1[nt][1] + bb.y, 0.0f));
                p1.x = to_tf32(fmaxf(acc1[nt][2] + bb.x, 0.0f));
                p1.y = to_tf32(fmaxf(acc1[nt][3] + bb.y, 0.0f));
                int hi = m0 + 4 * ((col >> 2) ^ g) + (col & 3);
                *reinterpret_cast<uint2*>(&Hb[hi])       = p0;   // row g
                *reinterpret_cast<uint2*>(&Hb[hi + 512]) = p1;   // row g+8
            }
            if (buf == 0) MBAR_ARRIVE(mb_full0); else MBAR_ARRIVE(mb_full1);
            buf ^= 1;
        }
    } else {
        // ================= CONSUMER =================
        const int arow = (16 * wh + g) * 64 + t4;
        int buf = 0;
        int pf0 = 0, pf1 = 0;

        for (int t = blockIdx.x; t < numTiles; t += G) {
            if (buf == 0) { MBAR_WAIT(mb_full0, pf0); pf0 ^= 1; }
            else          { MBAR_WAIT(mb_full1, pf1); pf1 ^= 1; }
            const uint32_t* Hs = smu + (buf ? H1F : H0F);

            const long long base = t * TS;
            const float* xT = x + base;
            const float* eT = eps + base;
            float* oT = out + base;
            const int r0 = 16 * wh + g;

            #pragma unroll
            for (int cc = 0; cc < 4; cc++) {
                float acc2[8][4];
                #pragma unroll
                for (int nt = 0; nt < 8; nt++)
                    acc2[nt][0] = acc2[nt][1] = acc2[nt][2] = acc2[nt][3] = 0.0f;

                #pragma unroll
                for (int ks = 0; ks < 8; ks++) {
                    int a0i = arow + 4 * ((2 * ks) ^ g);
                    uint32_t A0 = Hs[a0i], A1 = Hs[a0i + 512];
                    uint32_t A2 = Hs[a0i ^ 4], A3 = Hs[(a0i ^ 4) + 512];
                    const uint32_t* bp = smu + W2F + (8 * ks + t4) * 256 + 64 * cc + g;
                    #pragma unroll
                    for (int nt = 0; nt < 8; nt++) {
                        int o = 8 * (nt ^ t4);
                        mma8(acc2[nt], A0, A1, A2, A3, bp[o], bp[o + 1024]);
                    }
                }

                #pragma unroll
                for (int nt = 0; nt < 8; nt++) {
                    int col = 64 * cc + 8 * nt + 2 * t4;
                    float2 bb = *reinterpret_cast<const float2*>(&sm[B2S + col]);
                    int gi = r0 * SDIM + col;
                    float2 xv = *reinterpret_cast<const float2*>(&xT[gi]);
                    float2 ev = *reinterpret_cast<const float2*>(&eT[gi]);
                    float s0 = ex2f((acc2[nt][0] + bb.x) * 0.72134752044f);
                    float s1 = ex2f((acc2[nt][1] + bb.y) * 0.72134752044f);
                    float2 o0;
                    o0.x = fmaf(s0, ev.x, xv.x);
                    o0.y = fmaf(s1, ev.y, xv.y);
                    *reinterpret_cast<float2*>(&oT[gi]) = o0;

                    int gj = gi + 8 * SDIM;
                    float2 xw = *reinterpret_cast<const float2*>(&xT[gj]);
                    float2 ew = *reinterpret_cast<const float2*>(&eT[gj]);
                    float s2 = ex2f((acc2[nt][2] + bb.x) * 0.72134752044f);
                    float s3 = ex2f((acc2[nt][3] + bb.y) * 0.72134752044f);
                    float2 o1;
                    o1.x = fmaf(s2, ew.x, xw.x);
                    o1.y = fmaf(s3, ew.y, xw.y);
                    *reinterpret_cast<float2*>(&oT[gj]) = o1;
                }
            }

            if (buf == 0) MBAR_ARRIVE(mb_empty0); else MBAR_ARRIVE(mb_empty1);
            buf ^= 1;
        }
    }
}

extern "C" void kernel_launch(void* const* d_in, const int* in_sizes, int n_in,
                              void* d_out, int out_size) {
    const float* x   = (const float*)d_in[0];
    const float* eps = (const float*)d_in[1];
    const float* W1  = (const float*)d_in[2];
    const float* b1  = (const float*)d_in[3];
    const float* W2  = (const float*)d_in[4];
    const float* b2  = (const float*)d_in[5];
    float* out = (float*)d_out;

    int B = in_sizes[0] / SDIM;
    int numTiles = B / TMR;   // 1024

    static int sms = 0;
    if (!sms) {
        cudaDeviceGetAttribute(&sms, cudaDevAttrMultiProcessorCount, 0);
        cudaFuncSetAttribute(mvn_ws_kernel,
                             cudaFuncAttributeMaxDynamicSharedMemorySize, SMEM_BYTES);
    }
    int grid = sms < numTiles ? sms : numTiles;

    mvn_ws_kernel<<<grid, NTHREADS, SMEM_BYTES>>>(x, eps, W1, b1, W2, b2, out, numTiles);
}

// round 7
// speedup vs baseline: 1.0938x; 1.0938x over previous
#include <cuda_runtime.h>
#include <cstdint>

// out = x + exp(0.5*(relu(x@W1+b1)@W2 + b2)) * eps
// x,eps,out [B,256] f32; W1 [256,64]; b1[64]; W2 [64,256]; b2[256]
// Fully warp-autonomous persistent mma.sync tf32 kernel: each warp owns 16 rows
// end-to-end (cp.async X ring -> GEMM1 -> private H -> GEMM2 -> epilogue).
// No block-wide barriers in the main loop.

#define SDIM 256
#define HDIM 64
#define TROWS 256            // rows per CTA tile (16 warps x 16 rows)
#define NTHREADS 512

// smem float-index offsets
#define W1F 0          // W1 tf32 [k=256][64] XOR-swizzled   (64 KB)
#define W2F 16384      // W2 tf32 [k=64][256] XOR-swizzled   (64 KB)
#define XF  32768      // per-warp X ring: 16 warps x 2 slots x 256 fl (32 KB)
#define HF  40960      // per-warp H: 16 warps x 1024 fl (64 KB)
#define B1S 57344      // 64 f32
#define B2S 57408      // 256 f32
#define SMEM_FLOATS 57664
#define SMEM_BYTES  (SMEM_FLOATS * 4)   // 230656

__device__ __forceinline__ uint32_t to_tf32(float f) {
    uint32_t r; asm("cvt.rna.tf32.f32 %0, %1;" : "=r"(r) : "f"(f)); return r;
}
__device__ __forceinline__ float ex2f(float f) {
    float r; asm("ex2.approx.f32 %0, %1;" : "=f"(r) : "f"(f)); return r;
}
__device__ __forceinline__ void mma8(float* c,
    uint32_t a0, uint32_t a1, uint32_t a2, uint32_t a3, uint32_t b0, uint32_t b1) {
    asm volatile(
        "mma.sync.aligned.m16n8k8.row.col.f32.tf32.tf32.f32 "
        "{%0,%1,%2,%3},{%4,%5,%6,%7},{%8,%9},{%0,%1,%2,%3};"
        : "+f"(c[0]), "+f"(c[1]), "+f"(c[2]), "+f"(c[3])
        : "r"(a0), "r"(a1), "r"(a2), "r"(a3), "r"(b0), "r"(b1));
}
static __device__ __forceinline__ uint32_t smem_u32(const void* p) {
    uint32_t a;
    asm("{ .reg .u64 t; cvta.to.shared.u64 t, %1; cvt.u32.u64 %0, t; }" : "=r"(a) : "l"(p));
    return a;
}
#define CPA16(s, g)  asm volatile("cp.async.cg.shared.global [%0], [%1], 16;" :: "r"(s), "l"(g))
#define CPCOMMIT()   asm volatile("cp.async.commit_group;" ::: "memory")
#define CPWAIT1()    asm volatile("cp.async.wait_group 1;" ::: "memory")

// per-warp cp.async of one X chunk: 16 rows x 16 cols into a 1KB swizzled slot
static __device__ __forceinline__ void load_chunk16(
    const float* __restrict__ gRows, int ck, uint32_t slotAddr, int lane) {
    const float* gsrc = gRows + ck * 16;
    #pragma unroll
    for (int jj = 0; jj < 2; jj++) {
        int f = lane + 32 * jj;         // 0..63
        int m = f >> 2, j = f & 3;
        uint32_t dst = slotAddr + 4u * (m * 16 + ((4 * j) ^ (((m >> 1) & 3) << 2)));
        CPA16(dst, gsrc + m * SDIM + 4 * j);
    }
}

__global__ void __launch_bounds__(NTHREADS, 1) mvn_wa_kernel(
    const float* __restrict__ x, const float* __restrict__ eps,
    const float* __restrict__ W1, const float* __restrict__ b1,
    const float* __restrict__ W2, const float* __restrict__ b2,
    float* __restrict__ out, int numTiles)
{
    extern __shared__ float sm[];
    uint32_t* smu = reinterpret_cast<uint32_t*>(sm);

    const int tid  = threadIdx.x;
    const int w    = tid >> 5;
    const int lane = tid & 31;
    const int g    = lane >> 2;
    const int t4   = lane & 3;

    // ---- stage weights (tf32, XOR-swizzled) + biases ----
    #pragma unroll 4
    for (int j = 0; j < 32; j++) {
        int idx = tid + NTHREADS * j;
        int kk = idx >> 6, n = idx & 63;
        smu[W1F + kk * 64 + (n ^ (8 * (kk & 3)))] = to_tf32(W1[idx]);
    }
    #pragma unroll 4
    for (int j = 0; j < 32; j++) {
        int idx = tid + NTHREADS * j;
        int kk = idx >> 8, n = idx & 255;
        smu[W2F + kk * 256 + (n ^ (8 * (kk & 3)))] = to_tf32(W2[idx]);
    }
    if (tid < 64) sm[B1S + tid] = b1[tid];
    if (tid >= 64 && tid < 320) sm[B2S + tid - 64] = b2[tid - 64];
    __syncthreads();   // only block-wide barrier in the kernel

    const int G = gridDim.x;
    const long long TS = (long long)TROWS * SDIM;

    const uint32_t slotA = smem_u32(sm + XF + w * 512);        // slot 0
    const uint32_t slotB = slotA + 1024;                       // slot 1
    const float*  xsA = sm + XF + w * 512;
    uint32_t* Hb = smu + HF + w * 1024;
    const int sw = ((g >> 1) & 3) << 2;                        // X-slot swizzle

    int t = blockIdx.x;
    if (t < numTiles) {
        const float* gRows = x + t * TS + (16 * w) * SDIM;
        load_chunk16(gRows, 0, slotA, lane); CPCOMMIT();
        load_chunk16(gRows, 1, slotB, lane); CPCOMMIT();
    }

    for (; t < numTiles; t += G) {
        const long long base = t * TS;
        const float* gRows = x + base + (16 * w) * SDIM;

        // ======== GEMM1: acc1 = X(16 rows) @ W1 (K=256 in 16 chunks) ========
        float acc1[8][4];
        #pragma unroll
        for (int nt = 0; nt < 8; nt++)
            acc1[nt][0] = acc1[nt][1] = acc1[nt][2] = acc1[nt][3] = 0.0f;

        #pragma unroll
        for (int c = 0; c < 16; c++) {
            CPWAIT1();
            __syncwarp();
            const float* xs = xsA + (c & 1) * 256;
            #pragma unroll
            for (int ks = 0; ks < 2; ks++) {
                int c0 = (8 * ks + t4) ^ sw;
                int c2 = (8 * ks + t4 + 4) ^ sw;
                uint32_t A0 = to_tf32(xs[g * 16 + c0]);
                uint32_t A1 = to_tf32(xs[(g + 8) * 16 + c0]);
                uint32_t A2 = to_tf32(xs[g * 16 + c2]);
                uint32_t A3 = to_tf32(xs[(g + 8) * 16 + c2]);
                const uint32_t* bp = smu + W1F + (16 * c + 8 * ks + t4) * 64 + g;
                #pragma unroll
                for (int nt = 0; nt < 8; nt++) {
                    int o = 8 * (nt ^ t4);
                    mma8(acc1[nt], A0, A1, A2, A3, bp[o], bp[o + 256]);
                }
            }
            __syncwarp();   // all lanes done reading this slot
            int nc = c + 2;
            uint32_t slot = (c & 1) ? slotB : slotA;
            if (nc < 16) {
                load_chunk16(gRows, nc, slot, lane);
            } else {
                int tn = t + G;
                if (tn < numTiles)
                    load_chunk16(x + tn * TS + (16 * w) * SDIM, nc - 16, slot, lane);
            }
            CPCOMMIT();   // uniform group accounting
        }

        // ---- relu + bias -> private H (tf32), warp-local ----
        #pragma unroll
        for (int nt = 0; nt < 8; nt++) {
            int col = 8 * nt + 2 * t4;
            float2 bb = *reinterpret_cast<const float2*>(&sm[B1S + col]);
            uint2 p0, p1;
            p0.x = to_tf32(fmaxf(acc1[nt][0] + bb.x, 0.0f));
            p0.y = to_tf32(fmaxf(acc1[nt][1] + bb.y, 0.0f));
            p1.x = to_tf32(fmaxf(acc1[nt][2] + bb.x, 0.0f));
            p1.y = to_tf32(fmaxf(acc1[nt][3] + bb.y, 0.0f));
            int hi = g * 64 + 4 * ((col >> 2) ^ g) + (col & 3);
            *reinterpret_cast<uint2*>(&Hb[hi])       = p0;   // row g
            *reinterpret_cast<uint2*>(&Hb[hi + 512]) = p1;   // row g+8
        }
        __syncwarp();

        // ======== GEMM2 + fused epilogue (warp's 16 rows x 256 cols) ========
        const float* xT = x + base;
        const float* eT = eps + base;
        float* oT = out + base;
        const int r0 = 16 * w + g;

        #pragma unroll
        for (int cc = 0; cc < 4; cc++) {
            float acc2[8][4];
            #pragma unroll
            for (int nt = 0; nt < 8; nt++)
                acc2[nt][0] = acc2[nt][1] = acc2[nt][2] = acc2[nt][3] = 0.0f;

            #pragma unroll
            for (int ks = 0; ks < 8; ks++) {
                int a0i = g * 64 + 4 * ((2 * ks) ^ g) + t4;
                uint32_t A0 = Hb[a0i], A1 = Hb[a0i + 512];
                uint32_t A2 = Hb[a0i ^ 4], A3 = Hb[(a0i ^ 4) + 512];
                const uint32_t* bp = smu + W2F + (8 * ks + t4) * 256 + 64 * cc + g;
                #pragma unroll
                for (int nt = 0; nt < 8; nt++) {
                    int o = 8 * (nt ^ t4);
                    mma8(acc2[nt], A0, A1, A2, A3, bp[o], bp[o + 1024]);
                }
            }

            // epilogue: out = x + exp2(0.72134752*(d + b2)) * eps
            #pragma unroll
            for (int nt = 0; nt < 8; nt++) {
                int col = 64 * cc + 8 * nt + 2 * t4;
                float2 bb = *reinterpret_cast<const float2*>(&sm[B2S + col]);
                int gi = r0 * SDIM + col;
                float2 xv = *reinterpret_cast<const float2*>(&xT[gi]);
                float2 ev = *reinterpret_cast<const float2*>(&eT[gi]);
                float s0 = ex2f((acc2[nt][0] + bb.x) * 0.72134752044f);
                float s1 = ex2f((acc2[nt][1] + bb.y) * 0.72134752044f);
                float2 o0;
                o0.x = fmaf(s0, ev.x, xv.x);
                o0.y = fmaf(s1, ev.y, xv.y);
                *reinterpret_cast<float2*>(&oT[gi]) = o0;

                int gj = gi + 8 * SDIM;
                float2 xw = *reinterpret_cast<const float2*>(&xT[gj]);
                float2 ew = *reinterpret_cast<const float2*>(&eT[gj]);
                float s2 = ex2f((acc2[nt][2] + bb.x) * 0.72134752044f);
                float s3 = ex2f((acc2[nt][3] + bb.y) * 0.72134752044f);
                float2 o1;
                o1.x = fmaf(s2, ew.x, xw.x);
                o1.y = fmaf(s3, ew.y, xw.y);
                *reinterpret_cast<float2*>(&oT[gj]) = o1;
            }
        }
        __syncwarp();   // done with H before next tile overwrites it
    }
}

extern "C" void kernel_launch(void* const* d_in, const int* in_sizes, int n_in,
                              void* d_out, int out_size) {
    const float* x   = (const float*)d_in[0];
    const float* eps = (const float*)d_in[1];
    const float* W1  = (const float*)d_in[2];
    const float* b1  = (const float*)d_in[3];
    const float* W2  = (const float*)d_in[4];
    const float* b2  = (const float*)d_in[5];
    float* out = (float*)d_out;

    int B = in_sizes[0] / SDIM;
    int numTiles = B / TROWS;   // 512

    static int sms = 0;
    if (!sms) {
        cudaDeviceGetAttribute(&sms, cudaDevAttrMultiProcessorCount, 0);
        cudaFuncSetAttribute(mvn_wa_kernel,
                             cudaFuncAttributeMaxDynamicSharedMemorySize, SMEM_BYTES);
    }
    int grid = sms < numTiles ? sms : numTiles;

    mvn_wa_kernel<<<grid, NTHREADS, SMEM_BYTES>>>(x, eps, W1, b1, W2, b2, out, numTiles);
}